// round 4
// baseline (speedup 1.0000x reference)
#include <cuda_runtime.h>
#include <math.h>

#define NMAX 50000
#define EMAX 800000
#define HCMAX 512

// ---------------- scratch (static device globals; no allocations) -------------
__device__ float g_q[(size_t)NMAX * HCMAX];
__device__ float g_k[(size_t)NMAX * HCMAX];
__device__ float g_v[(size_t)NMAX * HCMAX];
__device__ float g_s[(size_t)NMAX * HCMAX];
__device__ float g_hA[(size_t)NMAX * HCMAX];
__device__ float g_hB[(size_t)NMAX * HCMAX];
__device__ float g_alpha[(size_t)EMAX * 8];   // overflow alpha buffer
__device__ int   g_rowptr[NMAX + 1];
__device__ int   g_csrc[EMAX];
__device__ int   g_src[EMAX];
__device__ int   g_dst[EMAX];
__device__ int   g_deg[NMAX];
__device__ int   g_fill[NMAX];
__device__ int   g_is64;

// ---------------- dtype detection + edge unpack -------------------------------
// If edge_index is int64 (little-endian), the high word of every value is 0
// (node ids < 2^31). If int32, odd words are random node ids (nonzero w.h.p.).
__global__ void detect_kernel(const unsigned int* __restrict__ w, int E, int* flag) {
    __shared__ int nz;
    if (threadIdx.x == 0) nz = 0;
    __syncthreads();
    int i = threadIdx.x;                 // 0..1023
    int npairs = (E < 1024) ? E : 1024;  // buffer has >= 2*E words either way
    if (i < npairs && w[2 * i + 1] != 0) atomicAdd(&nz, 1);
    __syncthreads();
    if (threadIdx.x == 0) *flag = (nz == 0) ? 1 : 0;   // 1 = int64, 0 = int32
}

__global__ void convert_kernel(const void* __restrict__ ei, int E,
                               const int* __restrict__ flag,
                               int* __restrict__ src, int* __restrict__ dst) {
    int e = blockIdx.x * blockDim.x + threadIdx.x;
    if (e >= E) return;
    if (*flag) {
        const long long* p = (const long long*)ei;
        src[e] = (int)p[e];
        dst[e] = (int)p[E + e];
    } else {
        const int* p = (const int*)ei;
        src[e] = p[e];
        dst[e] = p[E + e];
    }
}

// ---------------- small utility kernels ---------------------------------------
__global__ void zero_int_kernel(int* p, int n) {
    int i = blockIdx.x * blockDim.x + threadIdx.x;
    if (i < n) p[i] = 0;
}

__global__ void hist_kernel(const int* __restrict__ dst, int E, int* __restrict__ deg) {
    int e = blockIdx.x * blockDim.x + threadIdx.x;
    if (e < E) atomicAdd(&deg[dst[e]], 1);
}

// single-block exclusive scan of deg[0..n) -> rowptr, also copies to fill
__global__ void scan_kernel(const int* __restrict__ deg, int* __restrict__ rowptr,
                            int* __restrict__ fill, int n) {
    __shared__ int ssum[1024];
    int t = threadIdx.x;
    int chunk = (n + 1023) / 1024;
    int start = t * chunk;
    int s = 0;
    for (int j = 0; j < chunk; j++) {
        int idx = start + j;
        if (idx < n) s += deg[idx];
    }
    ssum[t] = s;
    __syncthreads();
    for (int off = 1; off < 1024; off <<= 1) {
        int v = 0;
        if (t >= off) v = ssum[t - off];
        __syncthreads();
        ssum[t] += v;
        __syncthreads();
    }
    int base = (t == 0) ? 0 : ssum[t - 1];
    int run = base;
    for (int j = 0; j < chunk; j++) {
        int idx = start + j;
        if (idx < n) {
            rowptr[idx] = run;
            fill[idx] = run;
            run += deg[idx];
        }
    }
    if (t == 0) rowptr[n] = ssum[1023];
}

__global__ void scatter_kernel(const int* __restrict__ src, const int* __restrict__ dst,
                               int E, int* __restrict__ fill, int* __restrict__ csrc) {
    int e = blockIdx.x * blockDim.x + threadIdx.x;
    if (e < E) {
        int p = atomicAdd(&fill[dst[e]], 1);
        csrc[p] = src[e];
    }
}

// ---------------- fp32 SGEMM: C[M,N] = A[M,K] @ W[K,N] + bias[N] --------------
// 128x128 tile, BK=8, 256 threads, 8x8 per thread.
__global__ __launch_bounds__(256, 2)
void sgemm_bias_kernel(const float* __restrict__ A, const float* __restrict__ W,
                       const float* __restrict__ bias, float* __restrict__ C,
                       int M, int N, int K) {
    __shared__ float As[8][128];
    __shared__ float Ws[8][128];
    int tid = threadIdx.x;
    int brow = blockIdx.y * 128;
    int bcol = blockIdx.x * 128;

    int arow = tid >> 1;            // 0..127
    int acol = (tid & 1) * 4;       // 0 or 4
    int wrow = tid >> 5;            // 0..7
    int wcol = (tid & 31) * 4;      // 0..124

    int ty = tid >> 4;              // 0..15
    int tx = tid & 15;              // 0..15

    float acc[8][8];
#pragma unroll
    for (int i = 0; i < 8; i++)
#pragma unroll
        for (int j = 0; j < 8; j++) acc[i][j] = 0.f;

    for (int k0 = 0; k0 < K; k0 += 8) {
        float4 av = make_float4(0.f, 0.f, 0.f, 0.f);
        if (brow + arow < M)
            av = *(const float4*)(A + (size_t)(brow + arow) * K + k0 + acol);
        As[acol + 0][arow] = av.x;
        As[acol + 1][arow] = av.y;
        As[acol + 2][arow] = av.z;
        As[acol + 3][arow] = av.w;

        float4 wv = make_float4(0.f, 0.f, 0.f, 0.f);
        if (bcol + wcol < N)
            wv = *(const float4*)(W + (size_t)(k0 + wrow) * N + bcol + wcol);
        Ws[wrow][wcol + 0] = wv.x;
        Ws[wrow][wcol + 1] = wv.y;
        Ws[wrow][wcol + 2] = wv.z;
        Ws[wrow][wcol + 3] = wv.w;

        __syncthreads();
#pragma unroll
        for (int kk = 0; kk < 8; kk++) {
            float a[8], b[8];
#pragma unroll
            for (int i = 0; i < 8; i++) a[i] = As[kk][ty * 8 + i];
#pragma unroll
            for (int j = 0; j < 8; j++) b[j] = Ws[kk][tx * 8 + j];
#pragma unroll
            for (int i = 0; i < 8; i++)
#pragma unroll
                for (int j = 0; j < 8; j++) acc[i][j] += a[i] * b[j];
        }
        __syncthreads();
    }

#pragma unroll
    for (int i = 0; i < 8; i++) {
        int r = brow + ty * 8 + i;
        if (r >= M) continue;
#pragma unroll
        for (int j = 0; j < 8; j++) {
            int c = bcol + tx * 8 + j;
            if (c < N) C[(size_t)r * N + c] = acc[i][j] + bias[c];
        }
    }
}

// ---------------- fused attention per node (one warp per (node, head)) --------
// blockDim = H*32; dynamic shared = H*128 floats (alpha cache, overflow->global)
__global__ void attn_kernel(const float* __restrict__ q, const float* __restrict__ k,
                            const float* __restrict__ v, const float* __restrict__ s,
                            const int* __restrict__ rowptr, const int* __restrict__ csrc,
                            float* __restrict__ out, float* __restrict__ alphabuf,
                            int H, int do_relu) {
    int i = blockIdx.x;
    int h = threadIdx.x >> 5;
    int lane = threadIdx.x & 31;
    int HC = H * 64;

    extern __shared__ float sh[];
    float* sha = sh + h * 128;

    const float2 qv = *(const float2*)(q + (size_t)i * HC + h * 64 + lane * 2);
    int p0 = rowptr[i];
    int p1 = rowptr[i + 1];

    float mmax = -1e30f;
    int sidx_next = (p0 < p1) ? csrc[p0] : 0;
    for (int p = p0; p < p1; p++) {
        int sidx = sidx_next;
        if (p + 1 < p1) sidx_next = csrc[p + 1];   // prefetch next src index
        float2 kv = *(const float2*)(k + (size_t)sidx * HC + h * 64 + lane * 2);
        float d = qv.x * kv.x + qv.y * kv.y;
        d += __shfl_xor_sync(0xffffffffu, d, 16);
        d += __shfl_xor_sync(0xffffffffu, d, 8);
        d += __shfl_xor_sync(0xffffffffu, d, 4);
        d += __shfl_xor_sync(0xffffffffu, d, 2);
        d += __shfl_xor_sync(0xffffffffu, d, 1);
        d *= 0.125f;                      // 1/sqrt(64)
        mmax = fmaxf(mmax, d);
        int li = p - p0;
        if (li < 128) {
            if (lane == 0) sha[li] = d;
        } else {
            if (lane == 0) alphabuf[(size_t)p * H + h] = d;
        }
    }
    __syncwarp();

    float denom = 0.f;
    float accx = 0.f, accy = 0.f;
    sidx_next = (p0 < p1) ? csrc[p0] : 0;
    for (int p = p0; p < p1; p++) {
        int li = p - p0;
        float a = (li < 128) ? sha[li] : alphabuf[(size_t)p * H + h];
        float w = __expf(a - mmax);
        denom += w;
        int sidx = sidx_next;
        if (p + 1 < p1) sidx_next = csrc[p + 1];
        float2 vv = *(const float2*)(v + (size_t)sidx * HC + h * 64 + lane * 2);
        accx += w * vv.x;
        accy += w * vv.y;
    }
    float inv = 1.f / (denom + 1e-16f);

    int col = h * 64 + lane * 2;
    float2 sv = *(const float2*)(s + (size_t)i * HC + col);
    float ox = accx * inv + sv.x;
    float oy = accy * inv + sv.y;
    if (do_relu) {
        ox = fmaxf(ox, 0.f);
        oy = fmaxf(oy, 0.f);
    }
    *(float2*)(out + (size_t)i * HC + col) = make_float2(ox, oy);
}

// ---------------- launcher ----------------------------------------------------
extern "C" void kernel_launch(void* const* d_in, const int* in_sizes, int n_in,
                              void* d_out, int out_size) {
    const float* x = (const float*)d_in[0];
    const void* ei = d_in[1];
    int N = in_sizes[0] / 128;
    int E = in_sizes[1] / 2;

    const float* Wq0 = (const float*)d_in[2];  const float* bq0 = (const float*)d_in[3];
    const float* Wk0 = (const float*)d_in[4];  const float* bk0 = (const float*)d_in[5];
    const float* Wv0 = (const float*)d_in[6];  const float* bv0 = (const float*)d_in[7];
    const float* Ws0 = (const float*)d_in[8];  const float* bs0 = (const float*)d_in[9];
    const float* Wq1 = (const float*)d_in[10]; const float* bq1 = (const float*)d_in[11];
    const float* Wk1 = (const float*)d_in[12]; const float* bk1 = (const float*)d_in[13];
    const float* Wv1 = (const float*)d_in[14]; const float* bv1 = (const float*)d_in[15];
    const float* Ws1 = (const float*)d_in[16]; const float* bs1 = (const float*)d_in[17];
    const float* Wq2 = (const float*)d_in[18]; const float* bq2 = (const float*)d_in[19];
    const float* Wk2 = (const float*)d_in[20]; const float* bk2 = (const float*)d_in[21];
    const float* Wv2 = (const float*)d_in[22]; const float* bv2 = (const float*)d_in[23];
    const float* Ws2 = (const float*)d_in[24]; const float* bs2 = (const float*)d_in[25];

    float *q, *k, *v, *s, *hA, *hB, *alpha;
    int *rowptr, *csrc, *src, *dst, *deg, *fill, *is64;
    cudaGetSymbolAddress((void**)&q, g_q);
    cudaGetSymbolAddress((void**)&k, g_k);
    cudaGetSymbolAddress((void**)&v, g_v);
    cudaGetSymbolAddress((void**)&s, g_s);
    cudaGetSymbolAddress((void**)&hA, g_hA);
    cudaGetSymbolAddress((void**)&hB, g_hB);
    cudaGetSymbolAddress((void**)&alpha, g_alpha);
    cudaGetSymbolAddress((void**)&rowptr, g_rowptr);
    cudaGetSymbolAddress((void**)&csrc, g_csrc);
    cudaGetSymbolAddress((void**)&src, g_src);
    cudaGetSymbolAddress((void**)&dst, g_dst);
    cudaGetSymbolAddress((void**)&deg, g_deg);
    cudaGetSymbolAddress((void**)&fill, g_fill);
    cudaGetSymbolAddress((void**)&is64, g_is64);

    // ---- edge dtype detect + unpack + CSR build ----
    detect_kernel<<<1, 1024>>>((const unsigned int*)ei, E, is64);
    convert_kernel<<<(E + 255) / 256, 256>>>(ei, E, is64, src, dst);
    zero_int_kernel<<<(N + 255) / 256, 256>>>(deg, N);
    hist_kernel<<<(E + 255) / 256, 256>>>(dst, E, deg);
    scan_kernel<<<1, 1024>>>(deg, rowptr, fill, N);
    scatter_kernel<<<(E + 255) / 256, 256>>>(src, dst, E, fill, csrc);

    auto gemm = [&](const float* A, const float* W, const float* b, float* Cc,
                    int M, int Nn, int K) {
        dim3 grid((Nn + 127) / 128, (M + 127) / 128);
        sgemm_bias_kernel<<<grid, 256>>>(A, W, b, Cc, M, Nn, K);
    };

    // ---- layer 0: IN=128 -> 512, H=8, relu ----
    gemm(x, Wq0, bq0, q, N, 512, 128);
    gemm(x, Wk0, bk0, k, N, 512, 128);
    gemm(x, Wv0, bv0, v, N, 512, 128);
    gemm(x, Ws0, bs0, s, N, 512, 128);
    attn_kernel<<<N, 8 * 32, 8 * 128 * sizeof(float)>>>(q, k, v, s, rowptr, csrc,
                                                        hA, alpha, 8, 1);

    // ---- layer 1: 512 -> 512, H=8, relu ----
    gemm(hA, Wq1, bq1, q, N, 512, 512);
    gemm(hA, Wk1, bk1, k, N, 512, 512);
    gemm(hA, Wv1, bv1, v, N, 512, 512);
    gemm(hA, Ws1, bs1, s, N, 512, 512);
    attn_kernel<<<N, 8 * 32, 8 * 128 * sizeof(float)>>>(q, k, v, s, rowptr, csrc,
                                                        hB, alpha, 8, 1);

    // ---- layer 2: 512 -> 64, H=1, no relu, writes d_out ----
    gemm(hB, Wq2, bq2, q, N, 64, 512);
    gemm(hB, Wk2, bk2, k, N, 64, 512);
    gemm(hB, Wv2, bv2, v, N, 64, 512);
    gemm(hB, Ws2, bs2, s, N, 64, 512);
    attn_kernel<<<N, 1 * 32, 1 * 128 * sizeof(float)>>>(q, k, v, s, rowptr, csrc,
                                                        (float*)d_out, alpha, 1, 0);
}

// round 6
// speedup vs baseline: 1.8801x; 1.8801x over previous
#include <cuda_runtime.h>
#include <math.h>
#include <stdint.h>

#define NMAX 50000
#define EMAX 800000
#define HCMAX 512

// ---------------- scratch (static device globals; no allocations) -------------
__device__ float g_q[(size_t)NMAX * HCMAX];
__device__ float g_k[(size_t)NMAX * HCMAX];
__device__ float g_v[(size_t)NMAX * HCMAX];
__device__ float g_s[(size_t)NMAX * HCMAX];
__device__ float g_hA[(size_t)NMAX * HCMAX];
__device__ float g_hB[(size_t)NMAX * HCMAX];
__device__ float g_alpha[(size_t)EMAX * 8];   // overflow alpha buffer
__device__ int   g_rowptr[NMAX + 1];
__device__ int   g_csrc[EMAX];
__device__ int   g_src[EMAX];
__device__ int   g_dst[EMAX];
__device__ int   g_deg[NMAX];
__device__ int   g_fill[NMAX];
__device__ int   g_is64;

// ---------------- dtype detection + edge unpack -------------------------------
__global__ void detect_kernel(const unsigned int* __restrict__ w, int E, int* flag) {
    __shared__ int nz;
    if (threadIdx.x == 0) nz = 0;
    __syncthreads();
    int i = threadIdx.x;
    int npairs = (E < 1024) ? E : 1024;
    if (i < npairs && w[2 * i + 1] != 0) atomicAdd(&nz, 1);
    __syncthreads();
    if (threadIdx.x == 0) *flag = (nz == 0) ? 1 : 0;   // 1 = int64, 0 = int32
}

__global__ void convert_kernel(const void* __restrict__ ei, int E,
                               const int* __restrict__ flag,
                               int* __restrict__ src, int* __restrict__ dst) {
    int e = blockIdx.x * blockDim.x + threadIdx.x;
    if (e >= E) return;
    if (*flag) {
        const long long* p = (const long long*)ei;
        src[e] = (int)p[e];
        dst[e] = (int)p[E + e];
    } else {
        const int* p = (const int*)ei;
        src[e] = p[e];
        dst[e] = p[E + e];
    }
}

// ---------------- small utility kernels ---------------------------------------
__global__ void zero_int_kernel(int* p, int n) {
    int i = blockIdx.x * blockDim.x + threadIdx.x;
    if (i < n) p[i] = 0;
}

__global__ void hist_kernel(const int* __restrict__ dst, int E, int* __restrict__ deg) {
    int e = blockIdx.x * blockDim.x + threadIdx.x;
    if (e < E) atomicAdd(&deg[dst[e]], 1);
}

__global__ void scan_kernel(const int* __restrict__ deg, int* __restrict__ rowptr,
                            int* __restrict__ fill, int n) {
    __shared__ int ssum[1024];
    int t = threadIdx.x;
    int chunk = (n + 1023) / 1024;
    int start = t * chunk;
    int s = 0;
    for (int j = 0; j < chunk; j++) {
        int idx = start + j;
        if (idx < n) s += deg[idx];
    }
    ssum[t] = s;
    __syncthreads();
    for (int off = 1; off < 1024; off <<= 1) {
        int v = 0;
        if (t >= off) v = ssum[t - off];
        __syncthreads();
        ssum[t] += v;
        __syncthreads();
    }
    int base = (t == 0) ? 0 : ssum[t - 1];
    int run = base;
    for (int j = 0; j < chunk; j++) {
        int idx = start + j;
        if (idx < n) {
            rowptr[idx] = run;
            fill[idx] = run;
            run += deg[idx];
        }
    }
    if (t == 0) rowptr[n] = ssum[1023];
}

__global__ void scatter_kernel(const int* __restrict__ src, const int* __restrict__ dst,
                               int E, int* __restrict__ fill, int* __restrict__ csrc) {
    int e = blockIdx.x * blockDim.x + threadIdx.x;
    if (e < E) {
        int p = atomicAdd(&fill[dst[e]], 1);
        csrc[p] = src[e];
    }
}

// ---------------- TF32 tensor-core GEMM ---------------------------------------
// C[M,N] = A[M,K] @ W[K,N] + bias[N].  BM=BN=128, BK=32, 256 threads (8 warps,
// 2x4), warp tile 64x32, mma.m16n8k8 tf32. A/B converted to tf32 once at
// global->smem. Smem pads: A ld=36 (banks (4r+c)%32 distinct), B ld=136
// (banks (8t+g)%32 distinct).
#define LDA_S 36
#define LDB_S 136

__device__ __forceinline__ uint32_t f2tf32(float x) {
    uint32_t u;
    asm("cvt.rna.tf32.f32 %0, %1;" : "=r"(u) : "f"(x));
    return u;
}

__global__ __launch_bounds__(256, 2)
void tgemm_bias_kernel(const float* __restrict__ A, const float* __restrict__ W,
                       const float* __restrict__ bias, float* __restrict__ C,
                       int M, int N, int K) {
    __shared__ uint32_t As[128 * LDA_S];
    __shared__ uint32_t Bs[32 * LDB_S];

    int tid = threadIdx.x;
    int wid = tid >> 5;
    int lane = tid & 31;
    int gid = lane >> 2;      // group id 0..7
    int tig = lane & 3;       // thread-in-group 0..3
    int wy = wid >> 2;        // 0..1
    int wx = wid & 3;         // 0..3

    int brow = blockIdx.y * 128;
    int bcol = blockIdx.x * 128;

    float acc[4][4][4];
#pragma unroll
    for (int i = 0; i < 4; i++)
#pragma unroll
        for (int j = 0; j < 4; j++)
#pragma unroll
            for (int r = 0; r < 4; r++) acc[i][j][r] = 0.f;

    // global load indices
    int arow_l = tid >> 3;          // 0..31 (+32*i)
    int acol_l = (tid & 7) * 4;     // 0..28
    int brow_l = tid >> 5;          // 0..7 (+8*i)
    int bcol_l = (tid & 31) * 4;    // 0..124

    for (int kb = 0; kb < K; kb += 32) {
        // load A tile 128x32
#pragma unroll
        for (int i = 0; i < 4; i++) {
            int r = arow_l + i * 32;
            float4 av = make_float4(0.f, 0.f, 0.f, 0.f);
            if (brow + r < M)
                av = *(const float4*)(A + (size_t)(brow + r) * K + kb + acol_l);
            uint4 uv;
            uv.x = f2tf32(av.x); uv.y = f2tf32(av.y);
            uv.z = f2tf32(av.z); uv.w = f2tf32(av.w);
            *(uint4*)(As + r * LDA_S + acol_l) = uv;
        }
        // load B tile 32x128
#pragma unroll
        for (int i = 0; i < 4; i++) {
            int r = brow_l + i * 8;
            float4 wv = make_float4(0.f, 0.f, 0.f, 0.f);
            if (bcol + bcol_l < N)
                wv = *(const float4*)(W + (size_t)(kb + r) * N + bcol + bcol_l);
            uint4 uv;
            uv.x = f2tf32(wv.x); uv.y = f2tf32(wv.y);
            uv.z = f2tf32(wv.z); uv.w = f2tf32(wv.w);
            *(uint4*)(Bs + r * LDB_S + bcol_l) = uv;
        }
        __syncthreads();

#pragma unroll
        for (int ks = 0; ks < 4; ks++) {
            int kk = ks * 8;
            uint32_t af[4][4];
            uint32_t bf[4][2];
#pragma unroll
            for (int mt = 0; mt < 4; mt++) {
                int r0 = wy * 64 + mt * 16 + gid;
                af[mt][0] = As[(r0) * LDA_S + kk + tig];
                af[mt][1] = As[(r0 + 8) * LDA_S + kk + tig];
                af[mt][2] = As[(r0) * LDA_S + kk + tig + 4];
                af[mt][3] = As[(r0 + 8) * LDA_S + kk + tig + 4];
            }
#pragma unroll
            for (int nt = 0; nt < 4; nt++) {
                int c0 = wx * 32 + nt * 8 + gid;
                bf[nt][0] = Bs[(kk + tig) * LDB_S + c0];
                bf[nt][1] = Bs[(kk + tig + 4) * LDB_S + c0];
            }
#pragma unroll
            for (int mt = 0; mt < 4; mt++)
#pragma unroll
                for (int nt = 0; nt < 4; nt++) {
                    asm volatile(
                        "mma.sync.aligned.m16n8k8.row.col.f32.tf32.tf32.f32 "
                        "{%0,%1,%2,%3}, {%4,%5,%6,%7}, {%8,%9}, {%0,%1,%2,%3};"
                        : "+f"(acc[mt][nt][0]), "+f"(acc[mt][nt][1]),
                          "+f"(acc[mt][nt][2]), "+f"(acc[mt][nt][3])
                        : "r"(af[mt][0]), "r"(af[mt][1]),
                          "r"(af[mt][2]), "r"(af[mt][3]),
                          "r"(bf[nt][0]), "r"(bf[nt][1]));
                }
        }
        __syncthreads();
    }

    // epilogue: acc + bias
#pragma unroll
    for (int mt = 0; mt < 4; mt++) {
        int r0 = brow + wy * 64 + mt * 16 + gid;
#pragma unroll
        for (int nt = 0; nt < 4; nt++) {
            int c0 = bcol + wx * 32 + nt * 8 + 2 * tig;
            if (c0 < N) {
                float b0 = bias[c0];
                float b1 = bias[c0 + 1];
                if (r0 < M) {
                    C[(size_t)r0 * N + c0]     = acc[mt][nt][0] + b0;
                    C[(size_t)r0 * N + c0 + 1] = acc[mt][nt][1] + b1;
                }
                if (r0 + 8 < M) {
                    C[(size_t)(r0 + 8) * N + c0]     = acc[mt][nt][2] + b0;
                    C[(size_t)(r0 + 8) * N + c0 + 1] = acc[mt][nt][3] + b1;
                }
            }
        }
    }
}

// ---------------- fused attention per node (one warp per (node, head)) --------
__global__ void attn_kernel(const float* __restrict__ q, const float* __restrict__ k,
                            const float* __restrict__ v, const float* __restrict__ s,
                            const int* __restrict__ rowptr, const int* __restrict__ csrc,
                            float* __restrict__ out, float* __restrict__ alphabuf,
                            int H, int do_relu) {
    int i = blockIdx.x;
    int h = threadIdx.x >> 5;
    int lane = threadIdx.x & 31;
    int HC = H * 64;

    extern __shared__ float sh[];
    float* sha = sh + h * 128;

    const float2 qv = *(const float2*)(q + (size_t)i * HC + h * 64 + lane * 2);
    int p0 = rowptr[i];
    int p1 = rowptr[i + 1];

    float mmax = -1e30f;
    int sidx_next = (p0 < p1) ? csrc[p0] : 0;
    for (int p = p0; p < p1; p++) {
        int sidx = sidx_next;
        if (p + 1 < p1) sidx_next = csrc[p + 1];
        float2 kv = *(const float2*)(k + (size_t)sidx * HC + h * 64 + lane * 2);
        float d = qv.x * kv.x + qv.y * kv.y;
        d += __shfl_xor_sync(0xffffffffu, d, 16);
        d += __shfl_xor_sync(0xffffffffu, d, 8);
        d += __shfl_xor_sync(0xffffffffu, d, 4);
        d += __shfl_xor_sync(0xffffffffu, d, 2);
        d += __shfl_xor_sync(0xffffffffu, d, 1);
        d *= 0.125f;                      // 1/sqrt(64)
        mmax = fmaxf(mmax, d);
        int li = p - p0;
        if (li < 128) {
            if (lane == 0) sha[li] = d;
        } else {
            if (lane == 0) alphabuf[(size_t)p * H + h] = d;
        }
    }
    __syncwarp();

    float denom = 0.f;
    float accx = 0.f, accy = 0.f;
    sidx_next = (p0 < p1) ? csrc[p0] : 0;
    for (int p = p0; p < p1; p++) {
        int li = p - p0;
        float a = (li < 128) ? sha[li] : alphabuf[(size_t)p * H + h];
        float w = __expf(a - mmax);
        denom += w;
        int sidx = sidx_next;
        if (p + 1 < p1) sidx_next = csrc[p + 1];
        float2 vv = *(const float2*)(v + (size_t)sidx * HC + h * 64 + lane * 2);
        accx += w * vv.x;
        accy += w * vv.y;
    }
    float inv = 1.f / (denom + 1e-16f);

    int col = h * 64 + lane * 2;
    float2 sv = *(const float2*)(s + (size_t)i * HC + col);
    float ox = accx * inv + sv.x;
    float oy = accy * inv + sv.y;
    if (do_relu) {
        ox = fmaxf(ox, 0.f);
        oy = fmaxf(oy, 0.f);
    }
    *(float2*)(out + (size_t)i * HC + col) = make_float2(ox, oy);
}

// ---------------- launcher ----------------------------------------------------
extern "C" void kernel_launch(void* const* d_in, const int* in_sizes, int n_in,
                              void* d_out, int out_size) {
    const float* x = (const float*)d_in[0];
    const void* ei = d_in[1];
    int N = in_sizes[0] / 128;
    int E = in_sizes[1] / 2;

    const float* Wq0 = (const float*)d_in[2];  const float* bq0 = (const float*)d_in[3];
    const float* Wk0 = (const float*)d_in[4];  const float* bk0 = (const float*)d_in[5];
    const float* Wv0 = (const float*)d_in[6];  const float* bv0 = (const float*)d_in[7];
    const float* Ws0 = (const float*)d_in[8];  const float* bs0 = (const float*)d_in[9];
    const float* Wq1 = (const float*)d_in[10]; const float* bq1 = (const float*)d_in[11];
    const float* Wk1 = (const float*)d_in[12]; const float* bk1 = (const float*)d_in[13];
    const float* Wv1 = (const float*)d_in[14]; const float* bv1 = (const float*)d_in[15];
    const float* Ws1 = (const float*)d_in[16]; const float* bs1 = (const float*)d_in[17];
    const float* Wq2 = (const float*)d_in[18]; const float* bq2 = (const float*)d_in[19];
    const float* Wk2 = (const float*)d_in[20]; const float* bk2 = (const float*)d_in[21];
    const float* Wv2 = (const float*)d_in[22]; const float* bv2 = (const float*)d_in[23];
    const float* Ws2 = (const float*)d_in[24]; const float* bs2 = (const float*)d_in[25];

    float *q, *k, *v, *s, *hA, *hB, *alpha;
    int *rowptr, *csrc, *src, *dst, *deg, *fill, *is64;
    cudaGetSymbolAddress((void**)&q, g_q);
    cudaGetSymbolAddress((void**)&k, g_k);
    cudaGetSymbolAddress((void**)&v, g_v);
    cudaGetSymbolAddress((void**)&s, g_s);
    cudaGetSymbolAddress((void**)&hA, g_hA);
    cudaGetSymbolAddress((void**)&hB, g_hB);
    cudaGetSymbolAddress((void**)&alpha, g_alpha);
    cudaGetSymbolAddress((void**)&rowptr, g_rowptr);
    cudaGetSymbolAddress((void**)&csrc, g_csrc);
    cudaGetSymbolAddress((void**)&src, g_src);
    cudaGetSymbolAddress((void**)&dst, g_dst);
    cudaGetSymbolAddress((void**)&deg, g_deg);
    cudaGetSymbolAddress((void**)&fill, g_fill);
    cudaGetSymbolAddress((void**)&is64, g_is64);

    // ---- edge dtype detect + unpack + CSR build ----
    detect_kernel<<<1, 1024>>>((const unsigned int*)ei, E, is64);
    convert_kernel<<<(E + 255) / 256, 256>>>(ei, E, is64, src, dst);
    zero_int_kernel<<<(N + 255) / 256, 256>>>(deg, N);
    hist_kernel<<<(E + 255) / 256, 256>>>(dst, E, deg);
    scan_kernel<<<1, 1024>>>(deg, rowptr, fill, N);
    scatter_kernel<<<(E + 255) / 256, 256>>>(src, dst, E, fill, csrc);

    auto gemm = [&](const float* A, const float* W, const float* b, float* Cc,
                    int M, int Nn, int K) {
        dim3 grid((Nn + 127) / 128, (M + 127) / 128);
        tgemm_bias_kernel<<<grid, 256>>>(A, W, b, Cc, M, Nn, K);
    };

    // ---- layer 0: IN=128 -> 512, H=8, relu ----
    gemm(x, Wq0, bq0, q, N, 512, 128);
    gemm(x, Wk0, bk0, k, N, 512, 128);
    gemm(x, Wv0, bv0, v, N, 512, 128);
    gemm(x, Ws0, bs0, s, N, 512, 128);
    attn_kernel<<<N, 8 * 32, 8 * 128 * sizeof(float)>>>(q, k, v, s, rowptr, csrc,
                                                        hA, alpha, 8, 1);

    // ---- layer 1: 512 -> 512, H=8, relu ----
    gemm(hA, Wq1, bq1, q, N, 512, 512);
    gemm(hA, Wk1, bk1, k, N, 512, 512);
    gemm(hA, Wv1, bv1, v, N, 512, 512);
    gemm(hA, Ws1, bs1, s, N, 512, 512);
    attn_kernel<<<N, 8 * 32, 8 * 128 * sizeof(float)>>>(q, k, v, s, rowptr, csrc,
                                                        hB, alpha, 8, 1);

    // ---- layer 2: 512 -> 64, H=1, no relu, writes d_out ----
    gemm(hB, Wq2, bq2, q, N, 64, 512);
    gemm(hB, Wk2, bk2, k, N, 64, 512);
    gemm(hB, Wv2, bv2, v, N, 64, 512);
    gemm(hB, Ws2, bs2, s, N, 64, 512);
    attn_kernel<<<N, 1 * 32, 1 * 128 * sizeof(float)>>>(q, k, v, s, rowptr, csrc,
                                                        (float*)d_out, alpha, 1, 0);
}

// round 8
// speedup vs baseline: 2.8310x; 1.5058x over previous
#include <cuda_runtime.h>
#include <math.h>
#include <stdint.h>

#define NMAX 50000
#define EMAX 800000
#define HCMAX 512

// ---------------- scratch (static device globals; no allocations) -------------
__device__ float g_q[(size_t)NMAX * HCMAX];
__device__ float g_k[(size_t)NMAX * HCMAX];
__device__ float g_v[(size_t)NMAX * HCMAX];
__device__ float g_s[(size_t)NMAX * HCMAX];
__device__ float g_hA[(size_t)NMAX * HCMAX];
__device__ float g_hB[(size_t)NMAX * HCMAX];
__device__ int   g_rowptr[NMAX + 1];
__device__ int   g_csrc[EMAX];
__device__ int   g_src[EMAX];
__device__ int   g_dst[EMAX];
__device__ int   g_deg[NMAX];
__device__ int   g_fill[NMAX];
__device__ int   g_is64;

// ---------------- dtype detection + edge unpack -------------------------------
__global__ void detect_kernel(const unsigned int* __restrict__ w, int E, int* flag) {
    __shared__ int nz;
    if (threadIdx.x == 0) nz = 0;
    __syncthreads();
    int i = threadIdx.x;
    int npairs = (E < 1024) ? E : 1024;
    if (i < npairs && w[2 * i + 1] != 0) atomicAdd(&nz, 1);
    __syncthreads();
    if (threadIdx.x == 0) *flag = (nz == 0) ? 1 : 0;   // 1 = int64, 0 = int32
}

__global__ void convert_kernel(const void* __restrict__ ei, int E,
                               const int* __restrict__ flag,
                               int* __restrict__ src, int* __restrict__ dst) {
    int e = blockIdx.x * blockDim.x + threadIdx.x;
    if (e >= E) return;
    if (*flag) {
        const long long* p = (const long long*)ei;
        src[e] = (int)p[e];
        dst[e] = (int)p[E + e];
    } else {
        const int* p = (const int*)ei;
        src[e] = p[e];
        dst[e] = p[E + e];
    }
}

// ---------------- small utility kernels ---------------------------------------
__global__ void zero_int_kernel(int* p, int n) {
    int i = blockIdx.x * blockDim.x + threadIdx.x;
    if (i < n) p[i] = 0;
}

__global__ void hist_kernel(const int* __restrict__ dst, int E, int* __restrict__ deg) {
    int e = blockIdx.x * blockDim.x + threadIdx.x;
    if (e < E) atomicAdd(&deg[dst[e]], 1);
}

__global__ void scan_kernel(const int* __restrict__ deg, int* __restrict__ rowptr,
                            int* __restrict__ fill, int n) {
    __shared__ int ssum[1024];
    int t = threadIdx.x;
    int chunk = (n + 1023) / 1024;
    int start = t * chunk;
    int s = 0;
    for (int j = 0; j < chunk; j++) {
        int idx = start + j;
        if (idx < n) s += deg[idx];
    }
    ssum[t] = s;
    __syncthreads();
    for (int off = 1; off < 1024; off <<= 1) {
        int v = 0;
        if (t >= off) v = ssum[t - off];
        __syncthreads();
        ssum[t] += v;
        __syncthreads();
    }
    int base = (t == 0) ? 0 : ssum[t - 1];
    int run = base;
    for (int j = 0; j < chunk; j++) {
        int idx = start + j;
        if (idx < n) {
            rowptr[idx] = run;
            fill[idx] = run;
            run += deg[idx];
        }
    }
    if (t == 0) rowptr[n] = ssum[1023];
}

__global__ void scatter_kernel(const int* __restrict__ src, const int* __restrict__ dst,
                               int E, int* __restrict__ fill, int* __restrict__ csrc) {
    int e = blockIdx.x * blockDim.x + threadIdx.x;
    if (e < E) {
        int p = atomicAdd(&fill[dst[e]], 1);
        csrc[p] = src[e];
    }
}

// ---------------- TF32 tensor-core GEMM (register double-buffered) ------------
// C[M,N] = A[M,K] @ W[K,N] + bias[N].  BM=BN=128, BK=32, 256 threads (8 warps,
// 2x4), warp tile 64x32, mma.m16n8k8 tf32.
#define LDA_S 36
#define LDB_S 136

__device__ __forceinline__ uint32_t f2tf32(float x) {
    uint32_t u;
    asm("cvt.rna.tf32.f32 %0, %1;" : "=r"(u) : "f"(x));
    return u;
}

__global__ __launch_bounds__(256, 2)
void tgemm_bias_kernel(const float* __restrict__ A, const float* __restrict__ W,
                       const float* __restrict__ bias, float* __restrict__ C,
                       int M, int N, int K) {
    __shared__ uint32_t As[128 * LDA_S];
    __shared__ uint32_t Bs[32 * LDB_S];

    int tid = threadIdx.x;
    int wid = tid >> 5;
    int lane = tid & 31;
    int gid = lane >> 2;
    int tig = lane & 3;
    int wy = wid >> 2;
    int wx = wid & 3;

    int brow = blockIdx.y * 128;
    int bcol = blockIdx.x * 128;

    float acc[4][4][4];
#pragma unroll
    for (int i = 0; i < 4; i++)
#pragma unroll
        for (int j = 0; j < 4; j++)
#pragma unroll
            for (int r = 0; r < 4; r++) acc[i][j][r] = 0.f;

    int arow_l = tid >> 3;          // 0..31 (+32*i)
    int acol_l = (tid & 7) * 4;     // 0..28
    int brow_l = tid >> 5;          // 0..7 (+8*i)
    int bcol_l = (tid & 31) * 4;    // 0..124

    float4 ar[4], br[4];

    // prologue: load tile kb=0 into registers
#pragma unroll
    for (int i = 0; i < 4; i++) {
        int r = arow_l + i * 32;
        ar[i] = make_float4(0.f, 0.f, 0.f, 0.f);
        if (brow + r < M)
            ar[i] = *(const float4*)(A + (size_t)(brow + r) * K + acol_l);
        int rb = brow_l + i * 8;
        br[i] = make_float4(0.f, 0.f, 0.f, 0.f);
        if (bcol + bcol_l < N)
            br[i] = *(const float4*)(W + (size_t)rb * N + bcol + bcol_l);
    }

    for (int kb = 0; kb < K; kb += 32) {
        // store current registers to smem (with tf32 convert)
#pragma unroll
        for (int i = 0; i < 4; i++) {
            int r = arow_l + i * 32;
            uint4 uv;
            uv.x = f2tf32(ar[i].x); uv.y = f2tf32(ar[i].y);
            uv.z = f2tf32(ar[i].z); uv.w = f2tf32(ar[i].w);
            *(uint4*)(As + r * LDA_S + acol_l) = uv;
            int rb = brow_l + i * 8;
            uint4 wv;
            wv.x = f2tf32(br[i].x); wv.y = f2tf32(br[i].y);
            wv.z = f2tf32(br[i].z); wv.w = f2tf32(br[i].w);
            *(uint4*)(Bs + rb * LDB_S + bcol_l) = wv;
        }
        __syncthreads();

        // prefetch next k-tile into registers (overlaps with mma below)
        int kn = kb + 32;
        if (kn < K) {
#pragma unroll
            for (int i = 0; i < 4; i++) {
                int r = arow_l + i * 32;
                ar[i] = make_float4(0.f, 0.f, 0.f, 0.f);
                if (brow + r < M)
                    ar[i] = *(const float4*)(A + (size_t)(brow + r) * K + kn + acol_l);
                int rb = brow_l + i * 8;
                br[i] = make_float4(0.f, 0.f, 0.f, 0.f);
                if (bcol + bcol_l < N)
                    br[i] = *(const float4*)(W + (size_t)(kn + rb) * N + bcol + bcol_l);
            }
        }

#pragma unroll
        for (int ks = 0; ks < 4; ks++) {
            int kk = ks * 8;
            uint32_t af[4][4];
            uint32_t bf[4][2];
#pragma unroll
            for (int mt = 0; mt < 4; mt++) {
                int r0 = wy * 64 + mt * 16 + gid;
                af[mt][0] = As[(r0) * LDA_S + kk + tig];
                af[mt][1] = As[(r0 + 8) * LDA_S + kk + tig];
                af[mt][2] = As[(r0) * LDA_S + kk + tig + 4];
                af[mt][3] = As[(r0 + 8) * LDA_S + kk + tig + 4];
            }
#pragma unroll
            for (int nt = 0; nt < 4; nt++) {
                int c0 = wx * 32 + nt * 8 + gid;
                bf[nt][0] = Bs[(kk + tig) * LDB_S + c0];
                bf[nt][1] = Bs[(kk + tig + 4) * LDB_S + c0];
            }
#pragma unroll
            for (int mt = 0; mt < 4; mt++)
#pragma unroll
                for (int nt = 0; nt < 4; nt++) {
                    asm volatile(
                        "mma.sync.aligned.m16n8k8.row.col.f32.tf32.tf32.f32 "
                        "{%0,%1,%2,%3}, {%4,%5,%6,%7}, {%8,%9}, {%0,%1,%2,%3};"
                        : "+f"(acc[mt][nt][0]), "+f"(acc[mt][nt][1]),
                          "+f"(acc[mt][nt][2]), "+f"(acc[mt][nt][3])
                        : "r"(af[mt][0]), "r"(af[mt][1]),
                          "r"(af[mt][2]), "r"(af[mt][3]),
                          "r"(bf[nt][0]), "r"(bf[nt][1]));
                }
        }
        __syncthreads();
    }

    // epilogue: acc + bias
#pragma unroll
    for (int mt = 0; mt < 4; mt++) {
        int r0 = brow + wy * 64 + mt * 16 + gid;
#pragma unroll
        for (int nt = 0; nt < 4; nt++) {
            int c0 = bcol + wx * 32 + nt * 8 + 2 * tig;
            if (c0 < N) {
                float b0 = bias[c0];
                float b1 = bias[c0 + 1];
                if (r0 < M) {
                    C[(size_t)r0 * N + c0]     = acc[mt][nt][0] + b0;
                    C[(size_t)r0 * N + c0 + 1] = acc[mt][nt][1] + b1;
                }
                if (r0 + 8 < M) {
                    C[(size_t)(r0 + 8) * N + c0]     = acc[mt][nt][2] + b0;
                    C[(size_t)(r0 + 8) * N + c0 + 1] = acc[mt][nt][3] + b1;
                }
            }
        }
    }
}

// ---------------- fused attention: online softmax, single pass ----------------
// one warp per (node, head); blockDim = H*32
__global__ void attn_kernel(const float* __restrict__ q, const float* __restrict__ k,
                            const float* __restrict__ v, const float* __restrict__ s,
                            const int* __restrict__ rowptr, const int* __restrict__ csrc,
                            float* __restrict__ out, int H, int do_relu) {
    int i = blockIdx.x;
    int h = threadIdx.x >> 5;
    int lane = threadIdx.x & 31;
    int HC = H * 64;

    const float2 qv = *(const float2*)(q + (size_t)i * HC + h * 64 + lane * 2);
    int p0 = rowptr[i];
    int p1 = rowptr[i + 1];

    float mmax = -1e30f;
    float denom = 0.f, accx = 0.f, accy = 0.f;
    int sidx_next = (p0 < p1) ? csrc[p0] : 0;
    for (int p = p0; p < p1; p++) {
        int sidx = sidx_next;
        if (p + 1 < p1) sidx_next = csrc[p + 1];   // prefetch next src index
        size_t base = (size_t)sidx * HC + h * 64 + lane * 2;
        float2 kv = *(const float2*)(k + base);
        float2 vv = *(const float2*)(v + base);    // issue v load with k load
        float d = qv.x * kv.x + qv.y * kv.y;
        d += __shfl_xor_sync(0xffffffffu, d, 16);
        d += __shfl_xor_sync(0xffffffffu, d, 8);
        d += __shfl_xor_sync(0xffffffffu, d, 4);
        d += __shfl_xor_sync(0xffffffffu, d, 2);
        d += __shfl_xor_sync(0xffffffffu, d, 1);
        d *= 0.125f;                               // 1/sqrt(64)
        if (d > mmax) {
            float sc = __expf(mmax - d);           // 0 on first edge
            denom *= sc; accx *= sc; accy *= sc;
            mmax = d;
        }
        float w = __expf(d - mmax);
        denom += w;
        accx += w * vv.x;
        accy += w * vv.y;
    }
    float inv = 1.f / (denom + 1e-16f);

    int col = h * 64 + lane * 2;
    float2 sv = *(const float2*)(s + (size_t)i * HC + col);
    float ox = accx * inv + sv.x;
    float oy = accy * inv + sv.y;
    if (do_relu) {
        ox = fmaxf(ox, 0.f);
        oy = fmaxf(oy, 0.f);
    }
    *(float2*)(out + (size_t)i * HC + col) = make_float2(ox, oy);
}

// ---------------- launcher ----------------------------------------------------
extern "C" void kernel_launch(void* const* d_in, const int* in_sizes, int n_in,
                              void* d_out, int out_size) {
    const float* x = (const float*)d_in[0];
    const void* ei = d_in[1];
    int N = in_sizes[0] / 128;
    int E = in_sizes[1] / 2;

    const float* Wq0 = (const float*)d_in[2];  const float* bq0 = (const float*)d_in[3];
    const float* Wk0 = (const float*)d_in[4];  const float* bk0 = (const float*)d_in[5];
    const float* Wv0 = (const float*)d_in[6];  const float* bv0 = (const float*)d_in[7];
    const float* Ws0 = (const float*)d_in[8];  const float* bs0 = (const float*)d_in[9];
    const float* Wq1 = (const float*)d_in[10]; const float* bq1 = (const float*)d_in[11];
    const float* Wk1 = (const float*)d_in[12]; const float* bk1 = (const float*)d_in[13];
    const float* Wv1 = (const float*)d_in[14]; const float* bv1 = (const float*)d_in[15];
    const float* Ws1 = (const float*)d_in[16]; const float* bs1 = (const float*)d_in[17];
    const float* Wq2 = (const float*)d_in[18]; const float* bq2 = (const float*)d_in[19];
    const float* Wk2 = (const float*)d_in[20]; const float* bk2 = (const float*)d_in[21];
    const float* Wv2 = (const float*)d_in[22]; const float* bv2 = (const float*)d_in[23];
    const float* Ws2 = (const float*)d_in[24]; const float* bs2 = (const float*)d_in[25];

    float *q, *k, *v, *s, *hA, *hB;
    int *rowptr, *csrc, *src, *dst, *deg, *fill, *is64;
    cudaGetSymbolAddress((void**)&q, g_q);
    cudaGetSymbolAddress((void**)&k, g_k);
    cudaGetSymbolAddress((void**)&v, g_v);
    cudaGetSymbolAddress((void**)&s, g_s);
    cudaGetSymbolAddress((void**)&hA, g_hA);
    cudaGetSymbolAddress((void**)&hB, g_hB);
    cudaGetSymbolAddress((void**)&rowptr, g_rowptr);
    cudaGetSymbolAddress((void**)&csrc, g_csrc);
    cudaGetSymbolAddress((void**)&src, g_src);
    cudaGetSymbolAddress((void**)&dst, g_dst);
    cudaGetSymbolAddress((void**)&deg, g_deg);
    cudaGetSymbolAddress((void**)&fill, g_fill);
    cudaGetSymbolAddress((void**)&is64, g_is64);

    // ---- edge dtype detect + unpack + CSR build ----
    detect_kernel<<<1, 1024>>>((const unsigned int*)ei, E, is64);
    convert_kernel<<<(E + 255) / 256, 256>>>(ei, E, is64, src, dst);
    zero_int_kernel<<<(N + 255) / 256, 256>>>(deg, N);
    hist_kernel<<<(E + 255) / 256, 256>>>(dst, E, deg);
    scan_kernel<<<1, 1024>>>(deg, rowptr, fill, N);
    scatter_kernel<<<(E + 255) / 256, 256>>>(src, dst, E, fill, csrc);

    auto gemm = [&](const float* A, const float* W, const float* b, float* Cc,
                    int M, int Nn, int K) {
        dim3 grid((Nn + 127) / 128, (M + 127) / 128);
        tgemm_bias_kernel<<<grid, 256>>>(A, W, b, Cc, M, Nn, K);
    };

    // ---- layer 0: IN=128 -> 512, H=8, relu ----
    gemm(x, Wq0, bq0, q, N, 512, 128);
    gemm(x, Wk0, bk0, k, N, 512, 128);
    gemm(x, Wv0, bv0, v, N, 512, 128);
    gemm(x, Ws0, bs0, s, N, 512, 128);
    attn_kernel<<<N, 8 * 32>>>(q, k, v, s, rowptr, csrc, hA, 8, 1);

    // ---- layer 1: 512 -> 512, H=8, relu ----
    gemm(hA, Wq1, bq1, q, N, 512, 512);
    gemm(hA, Wk1, bk1, k, N, 512, 512);
    gemm(hA, Wv1, bv1, v, N, 512, 512);
    gemm(hA, Ws1, bs1, s, N, 512, 512);
    attn_kernel<<<N, 8 * 32>>>(q, k, v, s, rowptr, csrc, hB, 8, 1);

    // ---- layer 2: 512 -> 64, H=1, no relu, writes d_out ----
    gemm(hB, Wq2, bq2, q, N, 64, 512);
    gemm(hB, Wk2, bk2, k, N, 64, 512);
    gemm(hB, Wv2, bv2, v, N, 64, 512);
    gemm(hB, Ws2, bs2, s, N, 64, 512);
    attn_kernel<<<N, 1 * 32>>>(q, k, v, s, rowptr, csrc, (float*)d_out, 1, 0);
}